// round 2
// baseline (speedup 1.0000x reference)
#include <cuda_runtime.h>

#define B_ 128
#define L_ 4096
#define H_ 64
#define V_ 64
#define HALF_ 32
#define C1 0.05f
#define LN_EPS 1e-5f
#define SEQ_CHUNK 1024

// Token-indexed tables (V=64 tokens): g_hs/g_he are pre-scaled by (1-ALPHA).
__device__ float g_hs[V_ * HALF_];
__device__ float g_he[V_ * HALF_];
__device__ float g_ks[V_ * HALF_];
__device__ float g_ke[V_ * HALF_];

// ---------------------------------------------------------------------------
// Kernel 1: per-token precompute. grid=64 (token), block=128.
//   h(tok) = LN(e + MLP(e)),  hs = h@Ws+bs, he = h@We+be, ks/ke = normalize.
// ---------------------------------------------------------------------------
__global__ void build_tables(const float* __restrict__ embed,
                             const float* __restrict__ W1, const float* __restrict__ b1,
                             const float* __restrict__ W2, const float* __restrict__ b2,
                             const float* __restrict__ gamma, const float* __restrict__ beta,
                             const float* __restrict__ Ws, const float* __restrict__ bs,
                             const float* __restrict__ We, const float* __restrict__ be)
{
    __shared__ float s_e[H_];
    __shared__ float s_a[2 * H_];
    __shared__ float s_x[H_];
    __shared__ float s_h[H_];
    __shared__ float s_mu, s_rstd;

    int tok = blockIdx.x;
    int tid = threadIdx.x;

    if (tid < H_) s_e[tid] = embed[tok * H_ + tid];
    __syncthreads();

    // a = relu(e @ W1 + b1)  (128-wide)
    {
        float acc = b1[tid];
        #pragma unroll 8
        for (int h = 0; h < H_; ++h) acc = fmaf(s_e[h], W1[h * 2 * H_ + tid], acc);
        s_a[tid] = fmaxf(acc, 0.0f);
    }
    __syncthreads();

    // x = e + a @ W2 + b2  (64-wide)
    if (tid < H_) {
        float acc = b2[tid];
        #pragma unroll 8
        for (int k = 0; k < 2 * H_; ++k) acc = fmaf(s_a[k], W2[k * H_ + tid], acc);
        s_x[tid] = s_e[tid] + acc;
    }
    __syncthreads();

    if (tid == 0) {
        float mu = 0.f;
        for (int i = 0; i < H_; ++i) mu += s_x[i];
        mu *= (1.0f / H_);
        float var = 0.f;
        for (int i = 0; i < H_; ++i) { float d = s_x[i] - mu; var = fmaf(d, d, var); }
        var *= (1.0f / H_);
        s_mu = mu;
        s_rstd = rsqrtf(var + LN_EPS);
    }
    __syncthreads();

    if (tid < H_) s_h[tid] = (s_x[tid] - s_mu) * s_rstd * gamma[tid] + beta[tid];
    __syncthreads();

    int wid = tid >> 5, lane = tid & 31;
    if (wid == 0) {
        float acc = bs[lane];
        #pragma unroll 8
        for (int j = 0; j < H_; ++j) acc = fmaf(s_h[j], Ws[j * HALF_ + lane], acc);
        float ss = acc * acc;
        #pragma unroll
        for (int m = 16; m > 0; m >>= 1) ss += __shfl_xor_sync(0xffffffffu, ss, m);
        float n = fmaxf(sqrtf(ss), 1e-12f);
        g_hs[tok * HALF_ + lane] = C1 * acc;
        g_ks[tok * HALF_ + lane] = acc / n;
    } else if (wid == 1) {
        float acc = be[lane];
        #pragma unroll 8
        for (int j = 0; j < H_; ++j) acc = fmaf(s_h[j], We[j * HALF_ + lane], acc);
        float ss = acc * acc;
        #pragma unroll
        for (int m = 16; m > 0; m >>= 1) ss += __shfl_xor_sync(0xffffffffu, ss, m);
        float n = fmaxf(sqrtf(ss), 1e-12f);
        g_he[tok * HALF_ + lane] = C1 * acc;
        g_ke[tok * HALF_ + lane] = acc / n;
    }
}

// ---------------------------------------------------------------------------
// Kernel 2: sequential delta-rule scan. grid = B (one batch per CTA),
// block = 256: thread (row i = tid>>3, quad q = tid&7) owns columns
// [4q, 4q+4) of row i of BOTH M_s and M_e in registers.
// Row-mates are lanes {(i&3)*8 + 0..7} of warp i>>2 -> bfly over 1,2,4.
// ---------------------------------------------------------------------------
__global__ __launch_bounds__(256, 1)
void scan_kernel(const int* __restrict__ seq,
                 const float* __restrict__ Wrp, const float* __restrict__ brp,
                 const float* __restrict__ Wout, const float* __restrict__ bout,
                 float* __restrict__ out)
{
    __shared__ float s_ks[V_ * HALF_];
    __shared__ float s_ke[V_ * HALF_];
    __shared__ float s_hs[V_ * HALF_];
    __shared__ float s_he[V_ * HALF_];
    __shared__ int   s_seq[SEQ_CHUNK];
    __shared__ float s_r[2 * HALF_];
    __shared__ float s_tmp[H_];

    const int b = blockIdx.x;
    const int tid = threadIdx.x;

    for (int k = tid; k < V_ * HALF_; k += 256) {
        s_ks[k] = g_ks[k];
        s_ke[k] = g_ke[k];
        s_hs[k] = g_hs[k];
        s_he[k] = g_he[k];
    }

    const int row = tid >> 3;
    const int q = tid & 7;
    const int c0 = q * 4;
    const float invL = 1.0f / (float)L_;
    const int* seqb = seq + b * L_;

    float ms0 = 0.f, ms1 = 0.f, ms2 = 0.f, ms3 = 0.f;
    float me0 = 0.f, me1 = 0.f, me2 = 0.f, me3 = 0.f;

    for (int base = 0; base < L_ - 1; base += SEQ_CHUNK) {
        __syncthreads();   // tables ready (first iter) / prev chunk consumed
        for (int k = tid; k < SEQ_CHUNK; k += 256) s_seq[k] = seqb[base + k];
        __syncthreads();
        const int tEnd = min(SEQ_CHUNK, L_ - 1 - base);
        #pragma unroll 2
        for (int tt = 0; tt < tEnd; ++tt) {
            const int tok = s_seq[tt];
            const int o = tok * HALF_ + c0;
            const float4 kv = *(const float4*)(s_ks + o);
            const float4 ev = *(const float4*)(s_ke + o);
            const float hsC = s_hs[tok * HALF_ + row];
            const float heC = s_he[tok * HALF_ + row];

            float ps = ms0 * kv.x;
            ps = fmaf(ms1, kv.y, ps); ps = fmaf(ms2, kv.z, ps); ps = fmaf(ms3, kv.w, ps);
            float pe = me0 * ev.x;
            pe = fmaf(me1, ev.y, pe); pe = fmaf(me2, ev.z, pe); pe = fmaf(me3, ev.w, pe);

            ps += __shfl_xor_sync(0xffffffffu, ps, 1);
            pe += __shfl_xor_sync(0xffffffffu, pe, 1);
            ps += __shfl_xor_sync(0xffffffffu, ps, 2);
            pe += __shfl_xor_sync(0xffffffffu, pe, 2);
            ps += __shfl_xor_sync(0xffffffffu, ps, 4);
            pe += __shfl_xor_sync(0xffffffffu, pe, 4);

            const float ds = fmaf(-C1, ps, hsC);                    // C1*(hs - vps)
            const float sc = (float)(base + tt + 1) * invL;
            const float de = sc * fmaf(-C1, pe, heC);               // C1*sc*(he - vpe)

            ms0 = fmaf(ds, kv.x, ms0); ms1 = fmaf(ds, kv.y, ms1);
            ms2 = fmaf(ds, kv.z, ms2); ms3 = fmaf(ds, kv.w, ms3);
            me0 = fmaf(de, ev.x, me0); me1 = fmaf(de, ev.y, me1);
            me2 = fmaf(de, ev.z, me2); me3 = fmaf(de, ev.w, me3);
        }
    }

    // Readout: qs/qe are exactly the normalized tables at the last token.
    {
        const int qtok = seqb[L_ - 1];
        const int o = qtok * HALF_ + c0;
        const float4 kv = *(const float4*)(s_ks + o);
        const float4 ev = *(const float4*)(s_ke + o);
        float ps = ms0 * kv.x;
        ps = fmaf(ms1, kv.y, ps); ps = fmaf(ms2, kv.z, ps); ps = fmaf(ms3, kv.w, ps);
        float pe = me0 * ev.x;
        pe = fmaf(me1, ev.y, pe); pe = fmaf(me2, ev.z, pe); pe = fmaf(me3, ev.w, pe);
        ps += __shfl_xor_sync(0xffffffffu, ps, 1);
        ps += __shfl_xor_sync(0xffffffffu, ps, 2);
        ps += __shfl_xor_sync(0xffffffffu, ps, 4);
        pe += __shfl_xor_sync(0xffffffffu, pe, 1);
        pe += __shfl_xor_sync(0xffffffffu, pe, 2);
        pe += __shfl_xor_sync(0xffffffffu, pe, 4);
        if (q == 0) {
            s_r[row] = ps;
            s_r[HALF_ + row] = pe;
        }
    }
    __syncthreads();

    // out = (r @ Wrp + brp) @ Wout + bout
    if (tid < H_) {
        float acc = brp[tid];
        #pragma unroll 8
        for (int k = 0; k < 2 * HALF_; ++k) acc = fmaf(s_r[k], Wrp[k * H_ + tid], acc);
        s_tmp[tid] = acc;
    }
    __syncthreads();
    if (tid < V_) {
        float acc = bout[tid];
        #pragma unroll 8
        for (int d = 0; d < H_; ++d) acc = fmaf(s_tmp[d], Wout[d * V_ + tid], acc);
        out[b * V_ + tid] = acc;
    }
}

// ---------------------------------------------------------------------------
extern "C" void kernel_launch(void* const* d_in, const int* in_sizes, int n_in,
                              void* d_out, int out_size)
{
    const int*   seq   = (const int*)d_in[0];
    const float* embed = (const float*)d_in[1];
    const float* W1    = (const float*)d_in[2];
    const float* b1    = (const float*)d_in[3];
    const float* W2    = (const float*)d_in[4];
    const float* b2    = (const float*)d_in[5];
    const float* gamma = (const float*)d_in[6];
    const float* beta  = (const float*)d_in[7];
    const float* Ws    = (const float*)d_in[8];
    const float* bs    = (const float*)d_in[9];
    const float* We    = (const float*)d_in[10];
    const float* be    = (const float*)d_in[11];
    const float* Wrp   = (const float*)d_in[12];
    const float* brp   = (const float*)d_in[13];
    const float* Wout  = (const float*)d_in[14];
    const float* bout  = (const float*)d_in[15];
    float* out = (float*)d_out;

    build_tables<<<V_, 128>>>(embed, W1, b1, W2, b2, gamma, beta, Ws, bs, We, be);
    scan_kernel<<<B_, 256>>>(seq, Wrp, brp, Wout, bout, out);
}

// round 5
// speedup vs baseline: 1.6401x; 1.6401x over previous
#include <cuda_runtime.h>

#define B_ 128
#define L_ 4096
#define H_ 64
#define V_ 64
#define HALF_ 32
#define C1 0.05f
#define LN_EPS 1e-5f

typedef unsigned long long ull;

// Token-indexed tables (V=64 tokens): g_hs/g_he are pre-scaled by (1-ALPHA)=C1.
__device__ float g_hs[V_ * HALF_];
__device__ float g_he[V_ * HALF_];
__device__ float g_ks[V_ * HALF_];
__device__ float g_ke[V_ * HALF_];
// Pairwise key Gram tables: g_Gs[a*64+b] = ks_a . ks_b
__device__ float g_Gs[V_ * V_];
__device__ float g_Ge[V_ * V_];

// ---------------- packed f32x2 helpers (FFMA2 path, sm_100+) ----------------
__device__ __forceinline__ ull fma2(ull a, ull b, ull c) {
    ull d; asm("fma.rn.f32x2 %0,%1,%2,%3;" : "=l"(d) : "l"(a), "l"(b), "l"(c)); return d;
}
__device__ __forceinline__ ull mul2(ull a, ull b) {
    ull d; asm("mul.rn.f32x2 %0,%1,%2;" : "=l"(d) : "l"(a), "l"(b)); return d;
}
__device__ __forceinline__ ull add2(ull a, ull b) {
    ull d; asm("add.rn.f32x2 %0,%1,%2;" : "=l"(d) : "l"(a), "l"(b)); return d;
}
__device__ __forceinline__ ull pack2(float x) {
    ull d; asm("mov.b64 %0,{%1,%1};" : "=l"(d) : "f"(x)); return d;
}
__device__ __forceinline__ float2 unpack2(ull v) {
    float2 r; asm("mov.b64 {%0,%1},%2;" : "=f"(r.x), "=f"(r.y) : "l"(v)); return r;
}

// ---------------------------------------------------------------------------
// Kernel 1: per-token precompute. grid=64 (token), block=128.
// ---------------------------------------------------------------------------
__global__ void build_tables(const float* __restrict__ embed,
                             const float* __restrict__ W1, const float* __restrict__ b1,
                             const float* __restrict__ W2, const float* __restrict__ b2,
                             const float* __restrict__ gamma, const float* __restrict__ beta,
                             const float* __restrict__ Ws, const float* __restrict__ bs,
                             const float* __restrict__ We, const float* __restrict__ be)
{
    __shared__ float s_e[H_];
    __shared__ float s_a[2 * H_];
    __shared__ float s_x[H_];
    __shared__ float s_h[H_];
    __shared__ float s_mu, s_rstd;

    int tok = blockIdx.x;
    int tid = threadIdx.x;

    if (tid < H_) s_e[tid] = embed[tok * H_ + tid];
    __syncthreads();

    {
        float acc = b1[tid];
        #pragma unroll 8
        for (int h = 0; h < H_; ++h) acc = fmaf(s_e[h], W1[h * 2 * H_ + tid], acc);
        s_a[tid] = fmaxf(acc, 0.0f);
    }
    __syncthreads();

    if (tid < H_) {
        float acc = b2[tid];
        #pragma unroll 8
        for (int k = 0; k < 2 * H_; ++k) acc = fmaf(s_a[k], W2[k * H_ + tid], acc);
        s_x[tid] = s_e[tid] + acc;
    }
    __syncthreads();

    if (tid == 0) {
        float mu = 0.f;
        for (int i = 0; i < H_; ++i) mu += s_x[i];
        mu *= (1.0f / H_);
        float var = 0.f;
        for (int i = 0; i < H_; ++i) { float d = s_x[i] - mu; var = fmaf(d, d, var); }
        var *= (1.0f / H_);
        s_mu = mu;
        s_rstd = rsqrtf(var + LN_EPS);
    }
    __syncthreads();

    if (tid < H_) s_h[tid] = (s_x[tid] - s_mu) * s_rstd * gamma[tid] + beta[tid];
    __syncthreads();

    int wid = tid >> 5, lane = tid & 31;
    if (wid == 0) {
        float acc = bs[lane];
        #pragma unroll 8
        for (int j = 0; j < H_; ++j) acc = fmaf(s_h[j], Ws[j * HALF_ + lane], acc);
        float ss = acc * acc;
        #pragma unroll
        for (int m = 16; m > 0; m >>= 1) ss += __shfl_xor_sync(0xffffffffu, ss, m);
        float n = fmaxf(sqrtf(ss), 1e-12f);
        g_hs[tok * HALF_ + lane] = C1 * acc;
        g_ks[tok * HALF_ + lane] = acc / n;
    } else if (wid == 1) {
        float acc = be[lane];
        #pragma unroll 8
        for (int j = 0; j < H_; ++j) acc = fmaf(s_h[j], We[j * HALF_ + lane], acc);
        float ss = acc * acc;
        #pragma unroll
        for (int m = 16; m > 0; m >>= 1) ss += __shfl_xor_sync(0xffffffffu, ss, m);
        float n = fmaxf(sqrtf(ss), 1e-12f);
        g_he[tok * HALF_ + lane] = C1 * acc;
        g_ke[tok * HALF_ + lane] = acc / n;
    }
}

// ---------------------------------------------------------------------------
// Kernel 1b: 64x64 key Gram matrices. grid=64, block=64.
// ---------------------------------------------------------------------------
__global__ void build_gram()
{
    int a = blockIdx.x;
    int b = threadIdx.x;
    float ss = 0.f, se = 0.f;
    #pragma unroll
    for (int j = 0; j < HALF_; ++j) {
        ss = fmaf(g_ks[a * HALF_ + j], g_ks[b * HALF_ + j], ss);
        se = fmaf(g_ke[a * HALF_ + j], g_ke[b * HALF_ + j], se);
    }
    g_Gs[a * V_ + b] = ss;
    g_Ge[a * V_ + b] = se;
}

// ---------------------------------------------------------------------------
// Kernel 2: delta-rule scan, Gram-deferred + f32x2 packed.
// grid = B (one batch per CTA/SM), block = 128 (4 warps -> 4 SMSPs).
// Warps 0,1: M_s rows [0..15],[16..31]; warps 2,3: M_e likewise.
// Lane: row = ((w&1)<<4)|(lane>>1), half = lane&1 -> owns 16 cols = 8 f32x2.
// Pipeline: dot for step t+1 is issued on M^(t) (missing update_t);
// the miss is repaired next iteration via d_t * Gram[tok_t][tok_{t+1}].
// ---------------------------------------------------------------------------
__global__ __launch_bounds__(128, 1)
void scan_kernel(const int* __restrict__ seq,
                 const float* __restrict__ Wrp, const float* __restrict__ brp,
                 const float* __restrict__ Wout, const float* __restrict__ bout,
                 float* __restrict__ out)
{
    extern __shared__ float sm[];
    float* s_ks = sm;                 // 2048
    float* s_ke = sm + 2048;          // 2048
    float* s_hs = sm + 4096;          // 2048
    float* s_he = sm + 6144;          // 2048
    float* s_Gs = sm + 8192;          // 4096
    float* s_Ge = sm + 12288;         // 4096
    int*   s_seq = (int*)(sm + 16384);          // 4096 ints
    float* s_r   = sm + 16384 + 4096;           // 64
    float* s_tmp = s_r + 64;                    // 64

    const int b = blockIdx.x;
    const int tid = threadIdx.x;
    const int w = tid >> 5;
    const int lane = tid & 31;

    // stage tables + full sequence once
    for (int k = tid; k < V_ * HALF_; k += 128) {
        s_ks[k] = g_ks[k];
        s_ke[k] = g_ke[k];
        s_hs[k] = g_hs[k];
        s_he[k] = g_he[k];
    }
    for (int k = tid; k < V_ * V_; k += 128) {
        s_Gs[k] = g_Gs[k];
        s_Ge[k] = g_Ge[k];
    }
    {
        const int* seqb = seq + b * L_;
        for (int k = tid; k < L_; k += 128) s_seq[k] = seqb[k];
    }
    __syncthreads();

    const bool is_e = (w >= 2);
    const int row = ((w & 1) << 4) | (lane >> 1);
    const int col0 = (lane & 1) << 4;
    const float* kT = is_e ? s_ke : s_ks;
    const float* hT = is_e ? s_he : s_hs;
    const float* gT = is_e ? s_Ge : s_Gs;
    const float invL = 1.0f / (float)L_;
    const float scstep = is_e ? invL : 0.0f;

    // ---- prologue: step 0 ----
    int tok_prev = s_seq[0];
    int tok_cur  = s_seq[1];
    float dprev;
    ull m[8];
    {
        float hC0 = hT[tok_prev * HALF_ + row];
        float sc0 = is_e ? invL : 1.0f;
        dprev = sc0 * hC0;                       // vps_0 = 0
        ull d2 = pack2(dprev);
        const ull* k0p = (const ull*)(kT + tok_prev * HALF_ + col0);
        #pragma unroll
        for (int j = 0; j < 8; ++j) m[j] = mul2(d2, k0p[j]);   // M^(1)
    }
    ull kc[8];
    {
        const ull* k1p = (const ull*)(kT + tok_cur * HALF_ + col0);
        #pragma unroll
        for (int j = 0; j < 8; ++j) kc[j] = k1p[j];            // k_1
    }
    ull acc0 = 0ull, acc1 = 0ull;                // raw dot of k_1 on M^(0)=0
    float sc = is_e ? 2.0f * invL : 1.0f;        // scale for step 1

    // ---- main loop: steps t = 1 .. L-2 ----
    #pragma unroll 2
    for (int t = 1; t <= L_ - 2; ++t) {
        const int tok_next = s_seq[t + 1];
        const float g  = gT[tok_prev * V_ + tok_cur];
        const float hC = hT[tok_cur * HALF_ + row];
        ull kn[8];
        {
            const ulonglong2* p = (const ulonglong2*)(kT + tok_next * HALF_ + col0);
            ulonglong2 a = p[0], bb = p[1], c = p[2], e = p[3];
            kn[0] = a.x;  kn[1] = a.y;  kn[2] = bb.x; kn[3] = bb.y;
            kn[4] = c.x;  kn[5] = c.y;  kn[6] = e.x;  kn[7] = e.y;
        }
        // finalize step t: ps_t = (M^(t-1).k_t) + d_{t-1} * (k_{t-1}.k_t)
        ull s01 = add2(acc0, acc1);
        float2 lh = unpack2(s01);
        float hsum = lh.x + lh.y;
        float full = hsum + __shfl_xor_sync(0xffffffffu, hsum, 1);
        float ps = fmaf(dprev, g, full);
        float dn = sc * fmaf(-C1, ps, hC);
        ull dn2 = pack2(dn);
        // dot for step t+1 on M^(t) (pre-update of step t)
        acc0 = mul2(m[0], kn[0]);
        acc1 = mul2(m[1], kn[1]);
        acc0 = fma2(m[2], kn[2], acc0);
        acc1 = fma2(m[3], kn[3], acc1);
        acc0 = fma2(m[4], kn[4], acc0);
        acc1 = fma2(m[5], kn[5], acc1);
        acc0 = fma2(m[6], kn[6], acc0);
        acc1 = fma2(m[7], kn[7], acc1);
        // apply update for step t: M^(t+1) = M^(t) + d_t (x) k_t
        #pragma unroll
        for (int j = 0; j < 8; ++j) m[j] = fma2(dn2, kc[j], m[j]);
        // rotate
        #pragma unroll
        for (int j = 0; j < 8; ++j) kc[j] = kn[j];
        dprev = dn;
        tok_prev = tok_cur;
        tok_cur = tok_next;
        sc += scstep;
    }

    // ---- readout: pipelined dot of k_{L-1} (== query key) on M^(L-2),
    //      corrected to M^(L-1) via Gram ----
    {
        ull s01 = add2(acc0, acc1);
        float2 lh = unpack2(s01);
        float hsum = lh.x + lh.y;
        float full = hsum + __shfl_xor_sync(0xffffffffu, hsum, 1);
        float g = gT[tok_prev * V_ + tok_cur];
        float r = fmaf(dprev, g, full);
        if ((lane & 1) == 0) s_r[(is_e ? HALF_ : 0) + row] = r;
    }
    __syncthreads();

    // out = (r @ Wrp + brp) @ Wout + bout
    if (tid < H_) {
        float acc = brp[tid];
        #pragma unroll 8
        for (int k = 0; k < 2 * HALF_; ++k) acc = fmaf(s_r[k], Wrp[k * H_ + tid], acc);
        s_tmp[tid] = acc;
    }
    __syncthreads();
    if (tid < V_) {
        float acc = bout[tid];
        #pragma unroll 8
        for (int d = 0; d < H_; ++d) acc = fmaf(s_tmp[d], Wout[d * V_ + tid], acc);
        out[b * V_ + tid] = acc;
    }
}

// ---------------------------------------------------------------------------
extern "C" void kernel_launch(void* const* d_in, const int* in_sizes, int n_in,
                              void* d_out, int out_size)
{
    const int*   seq   = (const int*)d_in[0];
    const float* embed = (const float*)d_in[1];
    const float* W1    = (const float*)d_in[2];
    const float* b1    = (const float*)d_in[3];
    const float* W2    = (const float*)d_in[4];
    const float* b2    = (const float*)d_in[5];
    const float* gamma = (const float*)d_in[6];
    const float* beta  = (const float*)d_in[7];
    const float* Ws    = (const float*)d_in[8];
    const float* bs    = (const float*)d_in[9];
    const float* We    = (const float*)d_in[10];
    const float* be    = (const float*)d_in[11];
    const float* Wrp   = (const float*)d_in[12];
    const float* brp   = (const float*)d_in[13];
    const float* Wout  = (const float*)d_in[14];
    const float* bout  = (const float*)d_in[15];
    float* out = (float*)d_out;

    // tables(64KB) + gram(32KB... in floats): 16384 floats tables/gram
    // + 4096 ints seq + 128 floats scratch = 82944 bytes
    static int smem_set = 0;
    const int smem_bytes = (16384 + 4096 + 128) * 4 + 512;
    if (!smem_set) {
        cudaFuncSetAttribute(scan_kernel,
                             cudaFuncAttributeMaxDynamicSharedMemorySize, smem_bytes);
        smem_set = 1;
    }

    build_tables<<<V_, 128>>>(embed, W1, b1, W2, b2, gamma, beta, Ws, bs, We, be);
    build_gram<<<V_, V_>>>();
    scan_kernel<<<B_, 128, smem_bytes>>>(seq, Wrp, brp, Wout, bout, out);
}

// round 6
// speedup vs baseline: 2.4051x; 1.4665x over previous
#include <cuda_runtime.h>

#define B_ 128
#define L_ 4096
#define H_ 64
#define V_ 64
#define HALF_ 32
#define C1 0.05f
#define LN_EPS 1e-5f
#define L_PAD (L_ + 4)

typedef unsigned long long ull;

// Token-indexed tables (V=64 tokens): g_hs/g_he are pre-scaled by (1-ALPHA)=C1.
__device__ float g_hs[V_ * HALF_];
__device__ float g_he[V_ * HALF_];
__device__ float g_ks[V_ * HALF_];
__device__ float g_ke[V_ * HALF_];

// ---------------- packed f32x2 helpers ----------------
__device__ __forceinline__ ull fma2(ull a, ull b, ull c) {
    ull d; asm("fma.rn.f32x2 %0,%1,%2,%3;" : "=l"(d) : "l"(a), "l"(b), "l"(c)); return d;
}
__device__ __forceinline__ ull mul2(ull a, ull b) {
    ull d; asm("mul.rn.f32x2 %0,%1,%2;" : "=l"(d) : "l"(a), "l"(b)); return d;
}
__device__ __forceinline__ ull add2(ull a, ull b) {
    ull d; asm("add.rn.f32x2 %0,%1,%2;" : "=l"(d) : "l"(a), "l"(b)); return d;
}
__device__ __forceinline__ ull pack2(float x) {
    ull d; asm("mov.b64 %0,{%1,%1};" : "=l"(d) : "f"(x)); return d;
}
__device__ __forceinline__ float2 unpack2(ull v) {
    float2 r; asm("mov.b64 {%0,%1},%2;" : "=f"(r.x), "=f"(r.y) : "l"(v)); return r;
}

// ---------------------------------------------------------------------------
// Kernel 1: per-token precompute. grid=64 (token), block=128.
// ---------------------------------------------------------------------------
__global__ void build_tables(const float* __restrict__ embed,
                             const float* __restrict__ W1, const float* __restrict__ b1,
                             const float* __restrict__ W2, const float* __restrict__ b2,
                             const float* __restrict__ gamma, const float* __restrict__ beta,
                             const float* __restrict__ Ws, const float* __restrict__ bs,
                             const float* __restrict__ We, const float* __restrict__ be)
{
    __shared__ float s_e[H_];
    __shared__ float s_a[2 * H_];
    __shared__ float s_x[H_];
    __shared__ float s_h[H_];
    __shared__ float s_mu, s_rstd;

    int tok = blockIdx.x;
    int tid = threadIdx.x;

    if (tid < H_) s_e[tid] = embed[tok * H_ + tid];
    __syncthreads();

    {
        float acc = b1[tid];
        #pragma unroll 32
        for (int h = 0; h < H_; ++h) acc = fmaf(s_e[h], __ldg(W1 + h * 2 * H_ + tid), acc);
        s_a[tid] = fmaxf(acc, 0.0f);
    }
    __syncthreads();

    if (tid < H_) {
        float acc = b2[tid];
        #pragma unroll 32
        for (int k = 0; k < 2 * H_; ++k) acc = fmaf(s_a[k], __ldg(W2 + k * H_ + tid), acc);
        s_x[tid] = s_e[tid] + acc;
    }
    __syncthreads();

    if (tid == 0) {
        float mu = 0.f;
        for (int i = 0; i < H_; ++i) mu += s_x[i];
        mu *= (1.0f / H_);
        float var = 0.f;
        for (int i = 0; i < H_; ++i) { float d = s_x[i] - mu; var = fmaf(d, d, var); }
        var *= (1.0f / H_);
        s_mu = mu;
        s_rstd = rsqrtf(var + LN_EPS);
    }
    __syncthreads();

    if (tid < H_) s_h[tid] = (s_x[tid] - s_mu) * s_rstd * gamma[tid] + beta[tid];
    __syncthreads();

    int wid = tid >> 5, lane = tid & 31;
    if (wid == 0) {
        float acc = bs[lane];
        #pragma unroll 32
        for (int j = 0; j < H_; ++j) acc = fmaf(s_h[j], __ldg(Ws + j * HALF_ + lane), acc);
        float ss = acc * acc;
        #pragma unroll
        for (int m = 16; m > 0; m >>= 1) ss += __shfl_xor_sync(0xffffffffu, ss, m);
        float n = fmaxf(sqrtf(ss), 1e-12f);
        g_hs[tok * HALF_ + lane] = C1 * acc;
        g_ks[tok * HALF_ + lane] = acc / n;
    } else if (wid == 1) {
        float acc = be[lane];
        #pragma unroll 32
        for (int j = 0; j < H_; ++j) acc = fmaf(s_h[j], __ldg(We + j * HALF_ + lane), acc);
        float ss = acc * acc;
        #pragma unroll
        for (int m = 16; m > 0; m >>= 1) ss += __shfl_xor_sync(0xffffffffu, ss, m);
        float n = fmaxf(sqrtf(ss), 1e-12f);
        g_he[tok * HALF_ + lane] = C1 * acc;
        g_ke[tok * HALF_ + lane] = acc / n;
    }
}

// ---------------------------------------------------------------------------
// Kernel 2: delta-rule scan, 3-stage pipelined (dot deferred by 2 steps).
// grid = B (one batch per CTA/SM), block = 128 (4 warps -> 4 SMSPs).
// Warps 0,1: M_s; warps 2,3: M_e. Lane owns half a row (16 cols = 8 f32x2).
// Invariants entering iter t:
//   m        = M^(t)          (updates d_0..d_{t-1} applied)
//   fullred  = M^(t-1).k_t    (reduced; correction d_{t-1}*G applied here)
//   acc0/1   = M^(t).k_{t+1}  (in-flight, reduced THIS iter)
//   dm1=d_{t-1}, g_cur=G[tok_{t-1}][tok_t], hsc/csc for step t
// ---------------------------------------------------------------------------
__global__ __launch_bounds__(128, 1)
void scan_kernel(const int* __restrict__ seq,
                 const float* __restrict__ Wrp, const float* __restrict__ brp,
                 const float* __restrict__ Wout, const float* __restrict__ bout,
                 float* __restrict__ out)
{
    extern __shared__ float sm[];
    float* s_ks = sm;                          // 2048
    float* s_ke = sm + 2048;                   // 2048
    float* s_hs = sm + 4096;                   // 2048
    float* s_he = sm + 6144;                   // 2048
    float* s_Gs = sm + 8192;                   // 4096
    float* s_Ge = sm + 12288;                  // 4096
    int*   s_seq = (int*)(sm + 16384);         // L_+4 ints
    float* s_r   = sm + 16384 + L_PAD;         // 64
    float* s_tmp = s_r + 64;                   // 64

    const int b = blockIdx.x;
    const int tid = threadIdx.x;
    const int w = tid >> 5;
    const int lane = tid & 31;

    // stage sequence (GMEM, start early) + tables
    {
        const int* seqb = seq + b * L_;
        for (int k = tid; k < L_; k += 128) s_seq[k] = seqb[k];
        if (tid < 4) s_seq[L_ + tid] = 0;
    }
    for (int k = tid; k < V_ * HALF_; k += 128) {
        s_ks[k] = g_ks[k];
        s_ke[k] = g_ke[k];
        s_hs[k] = g_hs[k];
        s_he[k] = g_he[k];
    }
    __syncthreads();

    // Gram tables computed in-CTA from staged keys (replaces a kernel launch)
    for (int idx = tid; idx < V_ * V_; idx += 128) {
        const int a = idx >> 6, c = idx & 63;
        float ss = 0.f, se = 0.f;
        #pragma unroll
        for (int j = 0; j < HALF_; ++j) {
            ss = fmaf(s_ks[a * HALF_ + j], s_ks[c * HALF_ + j], ss);
            se = fmaf(s_ke[a * HALF_ + j], s_ke[c * HALF_ + j], se);
        }
        s_Gs[idx] = ss;
        s_Ge[idx] = se;
    }
    __syncthreads();

    const bool is_e = (w >= 2);
    const int row = ((w & 1) << 4) | (lane >> 1);
    const int col0 = (lane & 1) << 4;
    const float* kT = is_e ? s_ke : s_ks;
    const float* hT = is_e ? s_he : s_hs;
    const float* gT = is_e ? s_Ge : s_Gs;
    const float invL = 1.0f / (float)L_;
    const float scstep = is_e ? invL : 0.0f;

    ull m[8], kb0[8], kb1[8], kb2[8];
    ull acc0, acc1;

    #define LOADK(DST, TOK) { \
        const ulonglong2* p_ = (const ulonglong2*)(kT + (TOK) * HALF_ + col0); \
        ulonglong2 a_ = p_[0], b_ = p_[1], c_ = p_[2], d_ = p_[3]; \
        DST[0] = a_.x; DST[1] = a_.y; DST[2] = b_.x; DST[3] = b_.y; \
        DST[4] = c_.x; DST[5] = c_.y; DST[6] = d_.x; DST[7] = d_.y; }

    // ---- prologue: step 0 ----
    const int tok0 = s_seq[0];
    int tok_cur = s_seq[1];
    int tok_nxt = s_seq[2];
    float dm1;
    {
        const float sc0 = is_e ? invL : 1.0f;
        dm1 = sc0 * hT[tok0 * HALF_ + row];             // d_0 (ps_0 = 0)
        const ull d02 = pack2(dm1);
        LOADK(kb0, tok0);
        #pragma unroll
        for (int j = 0; j < 8; ++j) m[j] = mul2(d02, kb0[j]);   // M^(1)
    }
    LOADK(kb1, tok_cur);    // k_1
    LOADK(kb2, tok_nxt);    // k_2
    // in-flight dot, target t=2: M^(1).k_2
    acc0 = mul2(m[0], kb2[0]); acc1 = mul2(m[1], kb2[1]);
    acc0 = fma2(m[2], kb2[2], acc0); acc1 = fma2(m[3], kb2[3], acc1);
    acc0 = fma2(m[4], kb2[4], acc0); acc1 = fma2(m[5], kb2[5], acc1);
    acc0 = fma2(m[6], kb2[6], acc0); acc1 = fma2(m[7], kb2[7], acc1);

    float fullred = 0.0f;                               // M^(0).k_1 = 0
    float g_cur = gT[tok0 * V_ + tok_cur];
    const float sc1 = is_e ? 2.0f * invL : 1.0f;
    float hsc_cur = sc1 * hT[tok_cur * HALF_ + row];
    float csc_cur = -C1 * sc1;
    float sc_nxt = is_e ? 3.0f * invL : 1.0f;           // scale for step 2

    #define STEP(T, KU, KL) { \
        const int tok_n2 = s_seq[(T) + 2]; \
        /* prefetch next-iter scalars (off the critical chain) */ \
        const float g_nxt = gT[tok_cur * V_ + tok_nxt]; \
        const float h_nxt = hT[tok_nxt * HALF_ + row]; \
        const float hsc_nxt = sc_nxt * h_nxt; \
        const float csc_nxt = -C1 * sc_nxt; \
        LOADK(KL, tok_n2); \
        /* serial chain: 2 FFMAs */ \
        const float ps = fmaf(dm1, g_cur, fullred); \
        const float dn = fmaf(csc_cur, ps, hsc_cur); \
        const ull dn2 = pack2(dn); \
        /* reduce in-flight dot (target T+1) */ \
        { ull s01_ = add2(acc0, acc1); \
          float2 lh_ = unpack2(s01_); \
          float hs_ = lh_.x + lh_.y; \
          fullred = hs_ + __shfl_xor_sync(0xffffffffu, hs_, 1); } \
        /* update M^(T) -> M^(T+1) with d_T (x) k_T */ \
        m[0] = fma2(dn2, KU[0], m[0]); m[1] = fma2(dn2, KU[1], m[1]); \
        m[2] = fma2(dn2, KU[2], m[2]); m[3] = fma2(dn2, KU[3], m[3]); \
        m[4] = fma2(dn2, KU[4], m[4]); m[5] = fma2(dn2, KU[5], m[5]); \
        m[6] = fma2(dn2, KU[6], m[6]); m[7] = fma2(dn2, KU[7], m[7]); \
        /* issue dot for target T+2 on M^(T+1) */ \
        acc0 = mul2(m[0], KL[0]); acc1 = mul2(m[1], KL[1]); \
        acc0 = fma2(m[2], KL[2], acc0); acc1 = fma2(m[3], KL[3], acc1); \
        acc0 = fma2(m[4], KL[4], acc0); acc1 = fma2(m[5], KL[5], acc1); \
        acc0 = fma2(m[6], KL[6], acc0); acc1 = fma2(m[7], KL[7], acc1); \
        /* rotate scalars */ \
        dm1 = dn; g_cur = g_nxt; hsc_cur = hsc_nxt; csc_cur = csc_nxt; \
        tok_cur = tok_nxt; tok_nxt = tok_n2; \
        sc_nxt += scstep; \
    }

    // main loop: iters t = 1 .. L-2 (period-3 key-buffer rotation)
    for (int t = 1; t <= L_ - 6; t += 3) {
        STEP(t,     kb1, kb0);
        STEP(t + 1, kb2, kb1);
        STEP(t + 2, kb0, kb2);
    }
    STEP(L_ - 3, kb1, kb0);   // t = 4093
    STEP(L_ - 2, kb2, kb1);   // t = 4094 (loads padded s_seq[4096]; dot discarded)

    #undef STEP
    #undef LOADK

    // readout: r = M^(L-1).k_{L-1} = fullred + d_{L-2} * G[tok_{L-2}][tok_{L-1}]
    {
        const float r = fmaf(dm1, g_cur, fullred);
        if ((lane & 1) == 0) s_r[(is_e ? HALF_ : 0) + row] = r;
    }
    __syncthreads();

    // out = (r @ Wrp + brp) @ Wout + bout
    if (tid < H_) {
        float acc = brp[tid];
        #pragma unroll 16
        for (int k = 0; k < 2 * HALF_; ++k) acc = fmaf(s_r[k], Wrp[k * H_ + tid], acc);
        s_tmp[tid] = acc;
    }
    __syncthreads();
    if (tid < V_) {
        float acc = bout[tid];
        #pragma unroll 16
        for (int d = 0; d < H_; ++d) acc = fmaf(s_tmp[d], Wout[d * V_ + tid], acc);
        out[b * V_ + tid] = acc;
    }
}

// ---------------------------------------------------------------------------
extern "C" void kernel_launch(void* const* d_in, const int* in_sizes, int n_in,
                              void* d_out, int out_size)
{
    const int*   seq   = (const int*)d_in[0];
    const float* embed = (const float*)d_in[1];
    const float* W1    = (const float*)d_in[2];
    const float* b1    = (const float*)d_in[3];
    const float* W2    = (const float*)d_in[4];
    const float* b2    = (const float*)d_in[5];
    const float* gamma = (const float*)d_in[6];
    const float* beta  = (const float*)d_in[7];
    const float* Ws    = (const float*)d_in[8];
    const float* bs    = (const float*)d_in[9];
    const float* We    = (const float*)d_in[10];
    const float* be    = (const float*)d_in[11];
    const float* Wrp   = (const float*)d_in[12];
    const float* brp   = (const float*)d_in[13];
    const float* Wout  = (const float*)d_in[14];
    const float* bout  = (const float*)d_in[15];
    float* out = (float*)d_out;

    static int smem_set = 0;
    const int smem_bytes = (16384 + L_PAD + 128) * 4 + 256;
    if (!smem_set) {
        cudaFuncSetAttribute(scan_kernel,
                             cudaFuncAttributeMaxDynamicSharedMemorySize, smem_bytes);
        smem_set = 1;
    }

    build_tables<<<V_, 128>>>(embed, W1, b1, W2, b2, gamma, beta, Ws, bs, We, be);
    scan_kernel<<<B_, 128, smem_bytes>>>(seq, Wrp, brp, Wout, bout, out);
}